// round 1
// baseline (speedup 1.0000x reference)
#include <cuda_runtime.h>
#include <math.h>

#define NB 2048
#define NT 64
#define ND 15
#define NH 256
#define NTILES 32   // NB / 64

// ---------------- device scratch (no allocations allowed) ----------------
__device__ float g_h[2][2][NB][NH];      // [parity][gru][b][h]
__device__ float g_xin[2][NB][272];
__device__ float g_a1[2][NB][1024];
__device__ float g_a2[2][NB][1024];
__device__ float g_a3[2][NB][512];
__device__ float g_a4[2][NB][256];
__device__ int   g_perm[NB];
__device__ int   g_hist[66];
__device__ int   g_off[66];
__device__ int   g_tilemax[NTILES];

// ---------------- init / length-sort kernels ----------------
__global__ void k_zero_h() {
  int i = blockIdx.x * blockDim.x + threadIdx.x;
  float4* p = reinterpret_cast<float4*>(&g_h[0][0][0][0]);
  if (i < 2 * NB * NH / 4) p[i] = make_float4(0.f, 0.f, 0.f, 0.f);
}

__global__ void k_hist_zero() {
  int i = threadIdx.x;
  if (i < 66) g_hist[i] = 0;
}

__global__ void k_hist(const int* __restrict__ lengths) {
  int b = blockIdx.x * blockDim.x + threadIdx.x;
  if (b < NB) atomicAdd(&g_hist[lengths[b]], 1);
}

__global__ void k_scan() {
  int s = 0;
  for (int l = 0; l < 66; ++l) { g_off[l] = s; s += g_hist[l]; }
}

__global__ void k_scatter(const int* __restrict__ lengths) {
  int b = blockIdx.x * blockDim.x + threadIdx.x;
  if (b < NB) {
    int p = atomicAdd(&g_off[lengths[b]], 1);
    g_perm[p] = b;
  }
}

__global__ void k_tilemax(const int* __restrict__ lengths) {
  int i = threadIdx.x;
  if (i < NTILES) g_tilemax[i] = lengths[g_perm[i * 64 + 63]];
}

// ---------------- GRU step kernel ----------------
// One launch per timestep t. grid = (32 batch-tiles, 8 col-tiles, 2 grus).
// Double-buffered h on parity of t: read t&1, write (t&1)^1.  Frozen tiles
// (t >= max length in sorted tile) degrade to a cheap copy.
struct GruSmem {
  float hs[64][257];   // h tile, all 256 cols, +1 pad (bank-conflict free)
  float ws[96][257];   // Whh rows {r,z,n} x 32 local cols
  float ss[64][16];    // state[:, t, :] slice
  float wis[96][16];   // Wih rows
  float bi[96];
  float bh[96];
  int   pr[64];
  int   ls[64];
};

__global__ void k_gru_step(const float* __restrict__ state,
                           const int* __restrict__ lengths,
                           const float* __restrict__ Wih0, const float* __restrict__ Whh0,
                           const float* __restrict__ bih0, const float* __restrict__ bhh0,
                           const float* __restrict__ Wih1, const float* __restrict__ Whh1,
                           const float* __restrict__ bih1, const float* __restrict__ bhh1,
                           int t)
{
  extern __shared__ char smem_raw[];
  GruSmem& s = *reinterpret_cast<GruSmem*>(smem_raw);
  const int bt  = blockIdx.x;
  const int jt  = blockIdx.y;
  const int g   = blockIdx.z;
  const int tid = threadIdx.x;   // 256
  const int pi = t & 1, po = pi ^ 1;

  if (t >= g_tilemax[bt]) {
    // fully frozen tile: just carry h to the out-parity buffer
    for (int idx = tid; idx < 64 * 32; idx += 256) {
      int r = idx >> 5, c = idx & 31;
      int p = g_perm[bt * 64 + r];
      g_h[po][g][p][jt * 32 + c] = g_h[pi][g][p][jt * 32 + c];
    }
    return;
  }

  const float* Wih = g ? Wih1 : Wih0;
  const float* Whh = g ? Whh1 : Whh0;
  const float* bih = g ? bih1 : bih0;
  const float* bhh = g ? bhh1 : bhh0;

  if (tid < 64) {
    int p = g_perm[bt * 64 + tid];
    s.pr[tid] = p;
    s.ls[tid] = lengths[p];
  }
  if (tid >= 64 && tid < 160) {
    int rr = tid - 64;                  // 0..95
    int gate = rr >> 5, jj = rr & 31;
    int row = gate * NH + jt * 32 + jj;
    s.bi[rr] = bih[row];
    s.bh[rr] = bhh[row];
    #pragma unroll
    for (int c = 0; c < ND; ++c) s.wis[rr][c] = Wih[row * ND + c];
  }
  __syncthreads();

  // Whh tile: 96 rows x 256 cols
  for (int idx = tid; idx < 96 * 64; idx += 256) {
    int rr = idx >> 6, c4 = idx & 63;
    int gate = rr >> 5, jj = rr & 31;
    int row = gate * NH + jt * 32 + jj;
    float4 v = reinterpret_cast<const float4*>(Whh + (size_t)row * NH)[c4];
    s.ws[rr][c4 * 4 + 0] = v.x; s.ws[rr][c4 * 4 + 1] = v.y;
    s.ws[rr][c4 * 4 + 2] = v.z; s.ws[rr][c4 * 4 + 3] = v.w;
  }
  // h tile: 64 rows x 256 cols (gathered through perm)
  for (int idx = tid; idx < 64 * 64; idx += 256) {
    int r = idx >> 6, c4 = idx & 63;
    float4 v = reinterpret_cast<const float4*>(&g_h[pi][g][s.pr[r]][0])[c4];
    s.hs[r][c4 * 4 + 0] = v.x; s.hs[r][c4 * 4 + 1] = v.y;
    s.hs[r][c4 * 4 + 2] = v.z; s.hs[r][c4 * 4 + 3] = v.w;
  }
  // state slice at time t
  for (int idx = tid; idx < 64 * ND; idx += 256) {
    int r = idx / ND, c = idx % ND;
    s.ss[r][c] = state[((size_t)s.pr[r] * NT + t) * ND + c];
  }
  __syncthreads();

  const int bg = tid >> 4;       // 0..15 -> 4 batch rows each
  const int jg = tid & 15;       // 0..15 -> 2 cols each
  const int b0 = bg * 4;
  const int j0 = jg * 2;

  float ar[4][2], az[4][2], ain[4][2], ahn[4][2];
  #pragma unroll
  for (int jj = 0; jj < 2; ++jj) {
    float br_  = s.bi[j0 + jj]      + s.bh[j0 + jj];
    float bz_  = s.bi[32 + j0 + jj] + s.bh[32 + j0 + jj];
    float bin_ = s.bi[64 + j0 + jj];
    float bhn_ = s.bh[64 + j0 + jj];
    #pragma unroll
    for (int i = 0; i < 4; ++i) {
      ar[i][jj] = br_; az[i][jj] = bz_; ain[i][jj] = bin_; ahn[i][jj] = bhn_;
    }
  }

  // input-gate contribution (K = 15)
  #pragma unroll
  for (int k = 0; k < ND; ++k) {
    float wr[2], wz[2], wn[2];
    #pragma unroll
    for (int jj = 0; jj < 2; ++jj) {
      wr[jj] = s.wis[j0 + jj][k];
      wz[jj] = s.wis[32 + j0 + jj][k];
      wn[jj] = s.wis[64 + j0 + jj][k];
    }
    #pragma unroll
    for (int i = 0; i < 4; ++i) {
      float sv = s.ss[b0 + i][k];
      #pragma unroll
      for (int jj = 0; jj < 2; ++jj) {
        ar[i][jj]  = fmaf(sv, wr[jj], ar[i][jj]);
        az[i][jj]  = fmaf(sv, wz[jj], az[i][jj]);
        ain[i][jj] = fmaf(sv, wn[jj], ain[i][jj]);
      }
    }
  }

  // recurrent contribution (K = 256)
  #pragma unroll 8
  for (int k = 0; k < NH; ++k) {
    float wr[2], wz[2], wn[2];
    #pragma unroll
    for (int jj = 0; jj < 2; ++jj) {
      wr[jj] = s.ws[j0 + jj][k];
      wz[jj] = s.ws[32 + j0 + jj][k];
      wn[jj] = s.ws[64 + j0 + jj][k];
    }
    #pragma unroll
    for (int i = 0; i < 4; ++i) {
      float hv = s.hs[b0 + i][k];
      #pragma unroll
      for (int jj = 0; jj < 2; ++jj) {
        ar[i][jj]  = fmaf(hv, wr[jj], ar[i][jj]);
        az[i][jj]  = fmaf(hv, wz[jj], az[i][jj]);
        ahn[i][jj] = fmaf(hv, wn[jj], ahn[i][jj]);
      }
    }
  }

  // gates + update
  #pragma unroll
  for (int i = 0; i < 4; ++i) {
    int bl = b0 + i;
    int p  = s.pr[bl];
    bool active = (t < s.ls[bl]);
    #pragma unroll
    for (int jj = 0; jj < 2; ++jj) {
      int jl = jt * 32 + j0 + jj;
      float hold = s.hs[bl][jl];
      float hnew;
      if (active) {
        float r = 1.f / (1.f + expf(-ar[i][jj]));
        float z = 1.f / (1.f + expf(-az[i][jj]));
        float n = tanhf(fmaf(r, ahn[i][jj], ain[i][jj]));
        hnew = fmaf(z, hold - n, n);    // (1-z)*n + z*h
      } else {
        hnew = hold;
      }
      g_h[po][g][p][jl] = hnew;
    }
  }
}

// ---------------- concat [state(:,0,:), action, h] ----------------
__global__ void k_concat(const float* __restrict__ state, const float* __restrict__ action) {
  int b = blockIdx.x, br = blockIdx.y;
  for (int c = threadIdx.x; c < 272; c += blockDim.x) {
    float v;
    if (c < ND)       v = state[(size_t)b * NT * ND + c];   // t = 0
    else if (c == ND) v = action[b];
    else              v = g_h[0][br][b][c - 16];            // final parity = 0
    g_xin[br][b][c] = v;
  }
}

// ---------------- tiled fp32 GEMM: C[M,N] = act(A[M,K] @ W[N,K]^T + b) ----------------
template<bool RELU>
__global__ void k_gemm(const float* __restrict__ A, const float* __restrict__ W,
                       const float* __restrict__ bias, float* __restrict__ C,
                       int K, int N)
{
  __shared__ float As[16][65];
  __shared__ float Ws[16][65];
  const int bm = blockIdx.x * 64;
  const int bn = blockIdx.y * 64;
  const int tid = threadIdx.x;          // 128
  const int mg = tid >> 4;              // 0..7  -> 8 rows each
  const int ng = tid & 15;              // 0..15 -> 4 cols each
  float acc[8][4];
  #pragma unroll
  for (int i = 0; i < 8; ++i)
    #pragma unroll
    for (int j = 0; j < 4; ++j) acc[i][j] = 0.f;

  for (int k0 = 0; k0 < K; k0 += 16) {
    #pragma unroll
    for (int idx = tid; idx < 1024; idx += 128) {
      int r = idx >> 4, k = idx & 15;
      As[k][r] = A[(size_t)(bm + r) * K + k0 + k];
      Ws[k][r] = W[(size_t)(bn + r) * K + k0 + k];
    }
    __syncthreads();
    #pragma unroll
    for (int k = 0; k < 16; ++k) {
      float a[8], w[4];
      #pragma unroll
      for (int i = 0; i < 8; ++i) a[i] = As[k][mg * 8 + i];
      #pragma unroll
      for (int j = 0; j < 4; ++j) w[j] = Ws[k][ng * 4 + j];
      #pragma unroll
      for (int i = 0; i < 8; ++i)
        #pragma unroll
        for (int j = 0; j < 4; ++j) acc[i][j] = fmaf(a[i], w[j], acc[i][j]);
    }
    __syncthreads();
  }
  #pragma unroll
  for (int i = 0; i < 8; ++i) {
    int m = bm + mg * 8 + i;
    #pragma unroll
    for (int j = 0; j < 4; ++j) {
      int n = bn + ng * 4 + j;
      float v = acc[i][j] + bias[n];
      if (RELU) v = fmaxf(v, 0.f);
      C[(size_t)m * N + n] = v;
    }
  }
}

// ---------------- q head: out[b] = dot(a4[b,:256], qw) + qb ----------------
__global__ void k_q(const float* __restrict__ A, const float* __restrict__ qw,
                    const float* __restrict__ qb, float* __restrict__ out)
{
  __shared__ float red[64];
  int b = blockIdx.x;
  float sum = 0.f;
  for (int c = threadIdx.x; c < 256; c += 64) sum += A[(size_t)b * 256 + c] * qw[c];
  red[threadIdx.x] = sum;
  __syncthreads();
  if (threadIdx.x < 32) {
    float v = red[threadIdx.x] + red[threadIdx.x + 32];
    #pragma unroll
    for (int o = 16; o; o >>= 1) v += __shfl_down_sync(0xffffffffu, v, o);
    if (threadIdx.x == 0) out[b] = v + qb[0];
  }
}

// ---------------- launch ----------------
extern "C" void kernel_launch(void* const* d_in, const int* in_sizes, int n_in,
                              void* d_out, int out_size)
{
  const float* state   = (const float*)d_in[0];
  const float* action  = (const float*)d_in[1];
  const int*   lengths = (const int*)d_in[2];

  const float* g_Wih[2]; const float* g_Whh[2];
  const float* g_bih[2]; const float* g_bhh[2];
  const float* fcw[2][5]; const float* fcb[2][5];
  for (int br = 0; br < 2; ++br) {
    int base = 3 + br * 14;
    g_Wih[br] = (const float*)d_in[base + 0];
    g_Whh[br] = (const float*)d_in[base + 1];
    g_bih[br] = (const float*)d_in[base + 2];
    g_bhh[br] = (const float*)d_in[base + 3];
    for (int l = 0; l < 5; ++l) {
      fcw[br][l] = (const float*)d_in[base + 4 + 2 * l];
      fcb[br][l] = (const float*)d_in[base + 5 + 2 * l];
    }
  }

  float *p_xin, *p_a1, *p_a2, *p_a3, *p_a4;
  cudaGetSymbolAddress((void**)&p_xin, g_xin);
  cudaGetSymbolAddress((void**)&p_a1, g_a1);
  cudaGetSymbolAddress((void**)&p_a2, g_a2);
  cudaGetSymbolAddress((void**)&p_a3, g_a3);
  cudaGetSymbolAddress((void**)&p_a4, g_a4);

  cudaFuncSetAttribute(k_gru_step, cudaFuncAttributeMaxDynamicSharedMemorySize,
                       (int)sizeof(GruSmem));

  // init + length bucket sort
  k_zero_h<<<(2 * NB * NH / 4 + 255) / 256, 256>>>();
  k_hist_zero<<<1, 66>>>();
  k_hist<<<NB / 256, 256>>>(lengths);
  k_scan<<<1, 1>>>();
  k_scatter<<<NB / 256, 256>>>(lengths);
  k_tilemax<<<1, NTILES>>>(lengths);

  // recurrent steps (launch boundary = global sync; h double-buffered on parity)
  for (int t = 0; t < NT; ++t) {
    k_gru_step<<<dim3(NTILES, 8, 2), 256, sizeof(GruSmem)>>>(
        state, lengths,
        g_Wih[0], g_Whh[0], g_bih[0], g_bhh[0],
        g_Wih[1], g_Whh[1], g_bih[1], g_bhh[1], t);
  }

  k_concat<<<dim3(NB, 2), 128>>>(state, action);

  float* outp = (float*)d_out;
  for (int br = 0; br < 2; ++br) {
    float* xin = p_xin + (size_t)br * NB * 272;
    float* a1  = p_a1  + (size_t)br * NB * 1024;
    float* a2  = p_a2  + (size_t)br * NB * 1024;
    float* a3  = p_a3  + (size_t)br * NB * 512;
    float* a4  = p_a4  + (size_t)br * NB * 256;
    k_gemm<true><<<dim3(32, 16), 128>>>(xin, fcw[br][0], fcb[br][0], a1, 272, 1024);
    k_gemm<true><<<dim3(32, 16), 128>>>(a1,  fcw[br][1], fcb[br][1], a2, 1024, 1024);
    k_gemm<true><<<dim3(32,  8), 128>>>(a2,  fcw[br][2], fcb[br][2], a3, 1024, 512);
    k_gemm<true><<<dim3(32,  4), 128>>>(a3,  fcw[br][3], fcb[br][3], a4, 512, 256);
    k_q<<<NB, 64>>>(a4, fcw[br][4], fcb[br][4], outp + (size_t)br * NB);
  }
}

// round 2
// speedup vs baseline: 1.2270x; 1.2270x over previous
#include <cuda_runtime.h>
#include <math.h>

#define NB 2048
#define NT 64
#define ND 15
#define NH 256
#define BT 64        // batch rows per GRU CTA
#define NTILES 32    // NB / BT

// ---------------- f32x2 packed-FMA helpers ----------------
__device__ __forceinline__ void ffma2(unsigned long long& d, unsigned long long a,
                                      unsigned long long b) {
  asm("fma.rn.f32x2 %0, %1, %2, %3;" : "=l"(d) : "l"(a), "l"(b), "l"(d));
}
__device__ __forceinline__ unsigned long long splat2(float w) {
  unsigned long long d;
  asm("mov.b64 %0, {%1, %1};" : "=l"(d) : "f"(w));
  return d;
}
__device__ __forceinline__ unsigned long long pack2(float lo, float hi) {
  unsigned long long d;
  asm("mov.b64 %0, {%1, %2};" : "=l"(d) : "f"(lo), "f"(hi));
  return d;
}
__device__ __forceinline__ float2 unpk2(unsigned long long v) {
  float2 r;
  asm("mov.b64 {%0, %1}, %2;" : "=f"(r.x), "=f"(r.y) : "l"(v));
  return r;
}

// ---------------- device scratch ----------------
__device__ float g_h[2][2][NB][NH];      // [parity][gru][b][h]
__device__ float g_xin[2][NB][272];
__device__ float g_a1[2][NB][1024];
__device__ float g_a2[2][NB][1024];
__device__ float g_a3[2][NB][512];
__device__ float g_a4[2][NB][256];
__device__ int   g_perm[NB];
__device__ int   g_hist[66];
__device__ int   g_off[66];
__device__ int   g_tilemax[NTILES];
__device__ int   g_finpar[NB];

// ---------------- init / length-sort kernels ----------------
__global__ void k_zero_h() {
  int i = blockIdx.x * blockDim.x + threadIdx.x;
  float4* p = reinterpret_cast<float4*>(&g_h[0][0][0][0]);
  if (i < 2 * NB * NH / 4) p[i] = make_float4(0.f, 0.f, 0.f, 0.f);
}
__global__ void k_hist_zero() { if (threadIdx.x < 66) g_hist[threadIdx.x] = 0; }
__global__ void k_hist(const int* __restrict__ lengths) {
  int b = blockIdx.x * blockDim.x + threadIdx.x;
  if (b < NB) atomicAdd(&g_hist[lengths[b]], 1);
}
__global__ void k_scan() {
  int s = 0;
  for (int l = 0; l < 66; ++l) { g_off[l] = s; s += g_hist[l]; }
}
__global__ void k_scatter(const int* __restrict__ lengths) {
  int b = blockIdx.x * blockDim.x + threadIdx.x;
  if (b < NB) { int p = atomicAdd(&g_off[lengths[b]], 1); g_perm[p] = b; }
}
__global__ void k_tilemax(const int* __restrict__ lengths) {
  int i = threadIdx.x;
  if (i < NTILES) g_tilemax[i] = lengths[g_perm[i * BT + BT - 1]];
}
__global__ void k_finpar() {
  int p = blockIdx.x * blockDim.x + threadIdx.x;
  if (p < NB) g_finpar[g_perm[p]] = g_tilemax[p >> 6] & 1;
}

// ---------------- GRU step kernel (FFMA2 inner loop) ----------------
// grid = (32 batch-tiles, 4 col-tiles of 64, 2 grus), 256 threads, per-step launch.
// h double-buffered on parity of t. Frozen tiles skip entirely (no copy);
// final parity recorded per batch row in g_finpar.
struct GruSmem {
  float hs[BT][260];     // h tile, all 256 cols (batch-major), pad->260
  float wT[16][196];     // Whh chunk, transposed: [k][gate*64+jj], pad->196
  float ss[BT][16];      // state[:, t, :] slice
  float wihT[16][196];   // Wih transposed [k][gate*64+jj] (k<15 used)
  float cbr[64], cbz[64], cbin[64], cbhn[64];
  int   pr[BT];
  int   ls[BT];
};

__global__ void __launch_bounds__(256, 2)
k_gru_step(const float* __restrict__ state,
           const int* __restrict__ lengths,
           const float* __restrict__ Wih0, const float* __restrict__ Whh0,
           const float* __restrict__ bih0, const float* __restrict__ bhh0,
           const float* __restrict__ Wih1, const float* __restrict__ Whh1,
           const float* __restrict__ bih1, const float* __restrict__ bhh1,
           int t)
{
  extern __shared__ char smem_raw[];
  GruSmem& s = *reinterpret_cast<GruSmem*>(smem_raw);
  const int bt  = blockIdx.x;
  const int jt  = blockIdx.y;      // 0..3 -> 64 cols
  const int g   = blockIdx.z;
  const int tid = threadIdx.x;
  const int pi = t & 1, po = pi ^ 1;

  if (t >= g_tilemax[bt]) return;   // frozen tile: nothing to do

  const float* Wih = g ? Wih1 : Wih0;
  const float* Whh = g ? Whh1 : Whh0;
  const float* bih = g ? bih1 : bih0;
  const float* bhh = g ? bhh1 : bhh0;
  const int jtbase = jt * 64;

  if (tid < BT) {
    int p = g_perm[bt * BT + tid];
    s.pr[tid] = p;
    s.ls[tid] = lengths[p];
  } else if (tid < BT + 64) {
    int jj = tid - BT;
    int r0 = jtbase + jj, r1 = NH + jtbase + jj, r2 = 2 * NH + jtbase + jj;
    s.cbr[jj]  = bih[r0] + bhh[r0];
    s.cbz[jj]  = bih[r1] + bhh[r1];
    s.cbin[jj] = bih[r2];
    s.cbhn[jj] = bhh[r2];
  }
  // Wih transpose: 192 rows x 15 cols
  for (int idx = tid; idx < 192 * ND; idx += 256) {
    int rr = idx / ND, c = idx % ND;
    int grow = (rr >> 6) * NH + jtbase + (rr & 63);
    s.wihT[c][rr] = Wih[grow * ND + c];
  }
  __syncthreads();

  // stage h tile (batch-major, float4, coalesced+conflict-free)
  for (int idx = tid; idx < BT * 64; idx += 256) {
    int r = idx >> 6, c4 = idx & 63;
    float4 v = reinterpret_cast<const float4*>(&g_h[pi][g][s.pr[r]][0])[c4];
    *reinterpret_cast<float4*>(&s.hs[r][c4 * 4]) = v;
  }
  // state slice at time t
  for (int idx = tid; idx < BT * ND; idx += 256) {
    int r = idx / ND, c = idx % ND;
    s.ss[r][c] = state[((size_t)s.pr[r] * NT + t) * ND + c];
  }
  __syncthreads();

  const int bg = tid >> 4;       // 0..15 -> 4 batch rows
  const int jg = tid & 15;       // 0..15 -> 4 cols (2 pairs)
  const int b0 = bg * 4;
  const int j0 = jg * 4;

  // accumulators: [batch 0..3][j-pair 0..1], packed f32x2 over j
  unsigned long long ar[4][2], az[4][2], ain[4][2], ahn[4][2];
  {
    unsigned long long br0 = pack2(s.cbr[j0],  s.cbr[j0 + 1]);
    unsigned long long br1 = pack2(s.cbr[j0 + 2], s.cbr[j0 + 3]);
    unsigned long long bz0 = pack2(s.cbz[j0],  s.cbz[j0 + 1]);
    unsigned long long bz1 = pack2(s.cbz[j0 + 2], s.cbz[j0 + 3]);
    unsigned long long bi0 = pack2(s.cbin[j0], s.cbin[j0 + 1]);
    unsigned long long bi1 = pack2(s.cbin[j0 + 2], s.cbin[j0 + 3]);
    unsigned long long bh0 = pack2(s.cbhn[j0], s.cbhn[j0 + 1]);
    unsigned long long bh1 = pack2(s.cbhn[j0 + 2], s.cbhn[j0 + 3]);
    #pragma unroll
    for (int b = 0; b < 4; ++b) {
      ar[b][0] = br0; ar[b][1] = br1;
      az[b][0] = bz0; az[b][1] = bz1;
      ain[b][0] = bi0; ain[b][1] = bi1;
      ahn[b][0] = bh0; ahn[b][1] = bh1;
    }
  }

  // input-gate contribution (K = 15)
  #pragma unroll
  for (int k = 0; k < ND; ++k) {
    ulonglong2 wr = *reinterpret_cast<const ulonglong2*>(&s.wihT[k][j0]);
    ulonglong2 wz = *reinterpret_cast<const ulonglong2*>(&s.wihT[k][64 + j0]);
    ulonglong2 wn = *reinterpret_cast<const ulonglong2*>(&s.wihT[k][128 + j0]);
    #pragma unroll
    for (int b = 0; b < 4; ++b) {
      unsigned long long sv = splat2(s.ss[b0 + b][k]);
      ffma2(ar[b][0], sv, wr.x);  ffma2(ar[b][1], sv, wr.y);
      ffma2(az[b][0], sv, wz.x);  ffma2(az[b][1], sv, wz.y);
      ffma2(ain[b][0], sv, wn.x); ffma2(ain[b][1], sv, wn.y);
    }
  }

  // recurrent contribution (K = 256), staged in 16-wide chunks
  for (int kc = 0; kc < NH; kc += 16) {
    #pragma unroll
    for (int e = 0; e < 3; ++e) {
      int idx = e * 256 + tid;             // 768 float4 loads
      int rr = idx >> 2, c = idx & 3;
      int grow = (rr >> 6) * NH + jtbase + (rr & 63);
      float4 v = *reinterpret_cast<const float4*>(&Whh[(size_t)grow * NH + kc + c * 4]);
      s.wT[c * 4 + 0][rr] = v.x; s.wT[c * 4 + 1][rr] = v.y;
      s.wT[c * 4 + 2][rr] = v.z; s.wT[c * 4 + 3][rr] = v.w;
    }
    __syncthreads();
    #pragma unroll
    for (int kk = 0; kk < 16; ++kk) {
      ulonglong2 wr = *reinterpret_cast<const ulonglong2*>(&s.wT[kk][j0]);
      ulonglong2 wz = *reinterpret_cast<const ulonglong2*>(&s.wT[kk][64 + j0]);
      ulonglong2 wn = *reinterpret_cast<const ulonglong2*>(&s.wT[kk][128 + j0]);
      #pragma unroll
      for (int b = 0; b < 4; ++b) {
        unsigned long long hv = splat2(s.hs[b0 + b][kc + kk]);
        ffma2(ar[b][0], hv, wr.x);  ffma2(ar[b][1], hv, wr.y);
        ffma2(az[b][0], hv, wz.x);  ffma2(az[b][1], hv, wz.y);
        ffma2(ahn[b][0], hv, wn.x); ffma2(ahn[b][1], hv, wn.y);
      }
    }
    __syncthreads();
  }

  // gates + update + write
  #pragma unroll
  for (int b = 0; b < 4; ++b) {
    int bl = b0 + b;
    bool active = (t < s.ls[bl]);
    float hn[4];
    #pragma unroll
    for (int jp = 0; jp < 2; ++jp) {
      float2 aR = unpk2(ar[b][jp]);
      float2 aZ = unpk2(az[b][jp]);
      float2 aI = unpk2(ain[b][jp]);
      float2 aH = unpk2(ahn[b][jp]);
      #pragma unroll
      for (int sdx = 0; sdx < 2; ++sdx) {
        int jl = jp * 2 + sdx;
        float xr = sdx ? aR.y : aR.x;
        float xz = sdx ? aZ.y : aZ.x;
        float xi = sdx ? aI.y : aI.x;
        float xh = sdx ? aH.y : aH.x;
        float hold = s.hs[bl][jtbase + j0 + jl];
        float hv;
        if (active) {
          float r = __fdividef(1.f, 1.f + __expf(-xr));
          float z = __fdividef(1.f, 1.f + __expf(-xz));
          float n = tanhf(fmaf(r, xh, xi));
          hv = fmaf(z, hold - n, n);
        } else {
          hv = hold;
        }
        hn[jl] = hv;
      }
    }
    *reinterpret_cast<float4*>(&g_h[po][g][s.pr[bl]][jtbase + j0]) =
        make_float4(hn[0], hn[1], hn[2], hn[3]);
  }
}

// ---------------- concat [state(:,0,:), action, h] ----------------
__global__ void k_concat(const float* __restrict__ state, const float* __restrict__ action) {
  int b = blockIdx.x, br = blockIdx.y;
  int fp = g_finpar[b];
  for (int c = threadIdx.x; c < 272; c += blockDim.x) {
    float v;
    if (c < ND)       v = state[(size_t)b * NT * ND + c];
    else if (c == ND) v = action[b];
    else              v = g_h[fp][br][b][c - 16];
    g_xin[br][b][c] = v;
  }
}

// ---------------- FFMA2 tiled GEMM: C[M,N] = relu(A[M,K] @ W[N,K]^T + b) ----------------
// 128x64 tile, 256 threads, pairs packed over M.
template<bool RELU>
__global__ void __launch_bounds__(256)
k_gemm2(const float* __restrict__ A, const float* __restrict__ W,
        const float* __restrict__ bias, float* __restrict__ C,
        int K, int N)
{
  __shared__ float As[16][132];   // [k][m], pad
  __shared__ float Ws[16][68];    // [k][n], pad
  const int bm = blockIdx.x * 128;
  const int bn = blockIdx.y * 64;
  const int tid = threadIdx.x;
  const int mg = tid >> 4;        // 0..15 -> 8 rows (4 pairs)
  const int ng = tid & 15;        // 0..15 -> 4 cols
  const int m0 = mg * 8;
  const int n0 = ng * 4;

  unsigned long long acc[4][4];
  #pragma unroll
  for (int i = 0; i < 4; ++i)
    #pragma unroll
    for (int j = 0; j < 4; ++j) acc[i][j] = 0ull;

  for (int k0 = 0; k0 < K; k0 += 16) {
    #pragma unroll
    for (int e = 0; e < 2; ++e) {
      int idx = e * 256 + tid;          // 512 float4
      int r = idx >> 2, c = idx & 3;
      float4 v = *reinterpret_cast<const float4*>(&A[(size_t)(bm + r) * K + k0 + c * 4]);
      As[c * 4 + 0][r] = v.x; As[c * 4 + 1][r] = v.y;
      As[c * 4 + 2][r] = v.z; As[c * 4 + 3][r] = v.w;
    }
    {
      int r = tid >> 2, c = tid & 3;    // 256 float4
      float4 v = *reinterpret_cast<const float4*>(&W[(size_t)(bn + r) * K + k0 + c * 4]);
      Ws[c * 4 + 0][r] = v.x; Ws[c * 4 + 1][r] = v.y;
      Ws[c * 4 + 2][r] = v.z; Ws[c * 4 + 3][r] = v.w;
    }
    __syncthreads();
    #pragma unroll
    for (int k = 0; k < 16; ++k) {
      ulonglong2 a01 = *reinterpret_cast<const ulonglong2*>(&As[k][m0]);
      ulonglong2 a23 = *reinterpret_cast<const ulonglong2*>(&As[k][m0 + 4]);
      float4 wv = *reinterpret_cast<const float4*>(&Ws[k][n0]);
      unsigned long long w2[4];
      w2[0] = splat2(wv.x); w2[1] = splat2(wv.y);
      w2[2] = splat2(wv.z); w2[3] = splat2(wv.w);
      #pragma unroll
      for (int n = 0; n < 4; ++n) {
        ffma2(acc[0][n], a01.x, w2[n]);
        ffma2(acc[1][n], a01.y, w2[n]);
        ffma2(acc[2][n], a23.x, w2[n]);
        ffma2(acc[3][n], a23.y, w2[n]);
      }
    }
    __syncthreads();
  }

  float bs[4];
  #pragma unroll
  for (int n = 0; n < 4; ++n) bs[n] = bias[bn + n0 + n];

  #pragma unroll
  for (int p = 0; p < 4; ++p) {
    float2 v0 = unpk2(acc[p][0]);
    float2 v1 = unpk2(acc[p][1]);
    float2 v2 = unpk2(acc[p][2]);
    float2 v3 = unpk2(acc[p][3]);
    int row = bm + m0 + p * 2;
    float4 lo = make_float4(v0.x + bs[0], v1.x + bs[1], v2.x + bs[2], v3.x + bs[3]);
    float4 hi = make_float4(v0.y + bs[0], v1.y + bs[1], v2.y + bs[2], v3.y + bs[3]);
    if (RELU) {
      lo.x = fmaxf(lo.x, 0.f); lo.y = fmaxf(lo.y, 0.f);
      lo.z = fmaxf(lo.z, 0.f); lo.w = fmaxf(lo.w, 0.f);
      hi.x = fmaxf(hi.x, 0.f); hi.y = fmaxf(hi.y, 0.f);
      hi.z = fmaxf(hi.z, 0.f); hi.w = fmaxf(hi.w, 0.f);
    }
    *reinterpret_cast<float4*>(&C[(size_t)row * N + bn + n0]) = lo;
    *reinterpret_cast<float4*>(&C[(size_t)(row + 1) * N + bn + n0]) = hi;
  }
}

// ---------------- q head ----------------
__global__ void k_q(const float* __restrict__ A, const float* __restrict__ qw,
                    const float* __restrict__ qb, float* __restrict__ out)
{
  __shared__ float red[64];
  int b = blockIdx.x;
  float sum = 0.f;
  for (int c = threadIdx.x; c < 256; c += 64) sum += A[(size_t)b * 256 + c] * qw[c];
  red[threadIdx.x] = sum;
  __syncthreads();
  if (threadIdx.x < 32) {
    float v = red[threadIdx.x] + red[threadIdx.x + 32];
    #pragma unroll
    for (int o = 16; o; o >>= 1) v += __shfl_down_sync(0xffffffffu, v, o);
    if (threadIdx.x == 0) out[b] = v + qb[0];
  }
}

// ---------------- launch ----------------
extern "C" void kernel_launch(void* const* d_in, const int* in_sizes, int n_in,
                              void* d_out, int out_size)
{
  const float* state   = (const float*)d_in[0];
  const float* action  = (const float*)d_in[1];
  const int*   lengths = (const int*)d_in[2];

  const float* gWih[2]; const float* gWhh[2];
  const float* gbih[2]; const float* gbhh[2];
  const float* fcw[2][5]; const float* fcb[2][5];
  for (int br = 0; br < 2; ++br) {
    int base = 3 + br * 14;
    gWih[br] = (const float*)d_in[base + 0];
    gWhh[br] = (const float*)d_in[base + 1];
    gbih[br] = (const float*)d_in[base + 2];
    gbhh[br] = (const float*)d_in[base + 3];
    for (int l = 0; l < 5; ++l) {
      fcw[br][l] = (const float*)d_in[base + 4 + 2 * l];
      fcb[br][l] = (const float*)d_in[base + 5 + 2 * l];
    }
  }

  float *p_xin, *p_a1, *p_a2, *p_a3, *p_a4;
  cudaGetSymbolAddress((void**)&p_xin, g_xin);
  cudaGetSymbolAddress((void**)&p_a1, g_a1);
  cudaGetSymbolAddress((void**)&p_a2, g_a2);
  cudaGetSymbolAddress((void**)&p_a3, g_a3);
  cudaGetSymbolAddress((void**)&p_a4, g_a4);

  cudaFuncSetAttribute(k_gru_step, cudaFuncAttributeMaxDynamicSharedMemorySize,
                       (int)sizeof(GruSmem));

  // init + length bucket sort
  k_zero_h<<<(2 * NB * NH / 4 + 255) / 256, 256>>>();
  k_hist_zero<<<1, 66>>>();
  k_hist<<<NB / 256, 256>>>(lengths);
  k_scan<<<1, 1>>>();
  k_scatter<<<NB / 256, 256>>>(lengths);
  k_tilemax<<<1, NTILES>>>(lengths);
  k_finpar<<<NB / 256, 256>>>();

  // recurrent steps
  for (int t = 0; t < NT; ++t) {
    k_gru_step<<<dim3(NTILES, 4, 2), 256, sizeof(GruSmem)>>>(
        state, lengths,
        gWih[0], gWhh[0], gbih[0], gbhh[0],
        gWih[1], gWhh[1], gbih[1], gbhh[1], t);
  }

  k_concat<<<dim3(NB, 2), 128>>>(state, action);

  float* outp = (float*)d_out;
  for (int br = 0; br < 2; ++br) {
    float* xin = p_xin + (size_t)br * NB * 272;
    float* a1  = p_a1  + (size_t)br * NB * 1024;
    float* a2  = p_a2  + (size_t)br * NB * 1024;
    float* a3  = p_a3  + (size_t)br * NB * 512;
    float* a4  = p_a4  + (size_t)br * NB * 256;
    k_gemm2<true><<<dim3(16, 16), 256>>>(xin, fcw[br][0], fcb[br][0], a1, 272, 1024);
    k_gemm2<true><<<dim3(16, 16), 256>>>(a1,  fcw[br][1], fcb[br][1], a2, 1024, 1024);
    k_gemm2<true><<<dim3(16,  8), 256>>>(a2,  fcw[br][2], fcb[br][2], a3, 1024, 512);
    k_gemm2<true><<<dim3(16,  4), 256>>>(a3,  fcw[br][3], fcb[br][3], a4, 512, 256);
    k_q<<<NB, 64>>>(a4, fcw[br][4], fcb[br][4], outp + (size_t)br * NB);
  }
}